// round 1
// baseline (speedup 1.0000x reference)
#include <cuda_runtime.h>
#include <math.h>

#define EMB   1024
#define HID   2048
#define VOCAB 50257
#define T_STEPS 256

// Persistent state across the 256 sequential steps (scratch via __device__ globals
// per harness rules). h is double-buffered (read t&1, write (t+1)&1). c is updated
// in place (each element owned by exactly one warp). g_key holds the packed argmax
// (orderable float bits << 32 | (0xFFFFFFFF - index)), double-buffered.
__device__ __align__(16) float g_h[2][HID];
__device__ __align__(16) float g_c[HID];
__device__ unsigned long long g_key[2];

__device__ __forceinline__ float sigmoidf_(float x) {
    return 1.0f / (1.0f + expf(-x));
}

__global__ void init_kernel() {
    int tid = blockIdx.x * blockDim.x + threadIdx.x;
    for (int i = tid; i < HID; i += 2048) {
        g_h[0][i] = 0.0f;
        g_h[1][i] = 0.0f;
        g_c[i]    = 0.0f;
    }
    if (tid == 0) {
        g_key[0] = 0ull;
        g_key[1] = 0xFFFFFFFFull;  // decodes to token 0 for step 0
    }
}

// One warp computes 4 gate rows (i, f, g, o for hidden index j) and fuses the
// LSTM cell update. Grid: 256 blocks x 256 threads (8 warps) = 2048 warps.
__global__ void __launch_bounds__(256) gates_cell_kernel(
    const float* __restrict__ emb,
    const float* __restrict__ W_ih,
    const float* __restrict__ W_hh,
    const float* __restrict__ b_ih,
    const float* __restrict__ b_hh,
    int t)
{
    __shared__ __align__(16) float sx[EMB];
    __shared__ __align__(16) float sh[HID];

    const int tid  = threadIdx.x;
    const int lane = tid & 31;
    const int warp = tid >> 5;

    // Decode previous step's argmax token. logits(t-1) wrote g_key[(t-1)&1] == g_key[(t+1)&1].
    unsigned long long key = g_key[(t + 1) & 1];
    int tok = (int)(0xFFFFFFFFu - (unsigned)(key & 0xFFFFFFFFull));
    // Reset the accumulator logits(t) will use. No thread here reads g_key[t&1].
    if (tid == 0) g_key[t & 1] = 0ull;

    // Stage x = emb[tok] and h into shared.
    const float4* xe = (const float4*)(emb + (size_t)tok * EMB);
    ((float4*)sx)[tid] = xe[tid];                       // 256 * float4 = 1024 floats
    const float4* h4 = (const float4*)(g_h[t & 1]);
    ((float4*)sh)[tid]       = h4[tid];
    ((float4*)sh)[tid + 256] = h4[tid + 256];
    __syncthreads();

    const int j = blockIdx.x * 8 + warp;                // 0..2047

    const float4* wi0 = (const float4*)(W_ih + (size_t)(j          ) * EMB);
    const float4* wi1 = (const float4*)(W_ih + (size_t)(j +     HID) * EMB);
    const float4* wi2 = (const float4*)(W_ih + (size_t)(j + 2 * HID) * EMB);
    const float4* wi3 = (const float4*)(W_ih + (size_t)(j + 3 * HID) * EMB);

    float a0 = 0.f, a1 = 0.f, a2 = 0.f, a3 = 0.f;

    #pragma unroll
    for (int it = 0; it < 8; it++) {                    // EMB/ (32*4) = 8
        int idx = it * 32 + lane;
        float4 xv = ((const float4*)sx)[idx];
        float4 v0 = __ldg(&wi0[idx]);
        float4 v1 = __ldg(&wi1[idx]);
        float4 v2 = __ldg(&wi2[idx]);
        float4 v3 = __ldg(&wi3[idx]);
        a0 += v0.x * xv.x + v0.y * xv.y + v0.z * xv.z + v0.w * xv.w;
        a1 += v1.x * xv.x + v1.y * xv.y + v1.z * xv.z + v1.w * xv.w;
        a2 += v2.x * xv.x + v2.y * xv.y + v2.z * xv.z + v2.w * xv.w;
        a3 += v3.x * xv.x + v3.y * xv.y + v3.z * xv.z + v3.w * xv.w;
    }

    const float4* wh0 = (const float4*)(W_hh + (size_t)(j          ) * HID);
    const float4* wh1 = (const float4*)(W_hh + (size_t)(j +     HID) * HID);
    const float4* wh2 = (const float4*)(W_hh + (size_t)(j + 2 * HID) * HID);
    const float4* wh3 = (const float4*)(W_hh + (size_t)(j + 3 * HID) * HID);

    #pragma unroll 4
    for (int it = 0; it < 16; it++) {                   // HID/(32*4) = 16
        int idx = it * 32 + lane;
        float4 hv = ((const float4*)sh)[idx];
        float4 v0 = __ldg(&wh0[idx]);
        float4 v1 = __ldg(&wh1[idx]);
        float4 v2 = __ldg(&wh2[idx]);
        float4 v3 = __ldg(&wh3[idx]);
        a0 += v0.x * hv.x + v0.y * hv.y + v0.z * hv.z + v0.w * hv.w;
        a1 += v1.x * hv.x + v1.y * hv.y + v1.z * hv.z + v1.w * hv.w;
        a2 += v2.x * hv.x + v2.y * hv.y + v2.z * hv.z + v2.w * hv.w;
        a3 += v3.x * hv.x + v3.y * hv.y + v3.z * hv.z + v3.w * hv.w;
    }

    #pragma unroll
    for (int off = 16; off > 0; off >>= 1) {
        a0 += __shfl_xor_sync(0xFFFFFFFFu, a0, off);
        a1 += __shfl_xor_sync(0xFFFFFFFFu, a1, off);
        a2 += __shfl_xor_sync(0xFFFFFFFFu, a2, off);
        a3 += __shfl_xor_sync(0xFFFFFFFFu, a3, off);
    }

    if (lane == 0) {
        a0 += b_ih[j          ] + b_hh[j          ];
        a1 += b_ih[j +     HID] + b_hh[j +     HID];
        a2 += b_ih[j + 2 * HID] + b_hh[j + 2 * HID];
        a3 += b_ih[j + 3 * HID] + b_hh[j + 3 * HID];
        float ig = sigmoidf_(a0);
        float fg = sigmoidf_(a1);
        float gg = tanhf(a2);
        float og = sigmoidf_(a3);
        float c  = fg * g_c[j] + ig * gg;
        g_c[j] = c;
        g_h[(t + 1) & 1][j] = og * tanhf(c);
    }
}

// Warp-per-row logits matvec with streaming loads on W_out, block-level argmax,
// one u64 atomicMax per block. Grid: ceil(VOCAB/8) x 256.
__global__ void __launch_bounds__(256) logits_kernel(
    const float* __restrict__ W_out,
    const float* __restrict__ b_out,
    float* __restrict__ out,
    int t)
{
    __shared__ __align__(16) float sh[HID];
    __shared__ float swv[8];
    __shared__ int   swi[8];

    const int tid  = threadIdx.x;
    const int lane = tid & 31;
    const int warp = tid >> 5;

    const float4* h4 = (const float4*)(g_h[(t + 1) & 1]);
    ((float4*)sh)[tid]       = h4[tid];
    ((float4*)sh)[tid + 256] = h4[tid + 256];
    __syncthreads();

    const int v = blockIdx.x * 8 + warp;
    float logit = -__int_as_float(0x7F800000);          // -inf

    if (v < VOCAB) {
        const float4* w = (const float4*)(W_out + (size_t)v * HID);
        float acc = 0.f;
        #pragma unroll
        for (int it = 0; it < 16; it++) {               // HID/(32*4)
            int idx = it * 32 + lane;
            float4 wv = __ldcs(&w[idx]);                // streaming: don't thrash L2
            float4 hv = ((const float4*)sh)[idx];
            acc += wv.x * hv.x + wv.y * hv.y + wv.z * hv.z + wv.w * hv.w;
        }
        #pragma unroll
        for (int off = 16; off > 0; off >>= 1)
            acc += __shfl_xor_sync(0xFFFFFFFFu, acc, off);
        if (lane == 0) {
            logit = acc + __ldg(&b_out[v]);
            __stcs(&out[(size_t)t * VOCAB + v], logit);
        }
    }

    if (lane == 0) { swv[warp] = logit; swi[warp] = v; }
    __syncthreads();

    if (tid == 0) {
        float best = swv[0]; int bi = swi[0];
        #pragma unroll
        for (int k = 1; k < 8; k++) {
            if (swv[k] > best) { best = swv[k]; bi = swi[k]; }  // strict > keeps first index on ties
        }
        unsigned ub = __float_as_uint(best);
        unsigned mk = (ub & 0x80000000u) ? ~ub : (ub | 0x80000000u);  // orderable float key
        unsigned long long key =
            ((unsigned long long)mk << 32) | (unsigned long long)(0xFFFFFFFFu - (unsigned)bi);
        atomicMax(&g_key[t & 1], key);
    }
}

extern "C" void kernel_launch(void* const* d_in, const int* in_sizes, int n_in,
                              void* d_out, int out_size)
{
    const float* emb   = (const float*)d_in[0];
    const float* W_ih  = (const float*)d_in[1];
    const float* W_hh  = (const float*)d_in[2];
    const float* b_ih  = (const float*)d_in[3];
    const float* b_hh  = (const float*)d_in[4];
    const float* W_out = (const float*)d_in[5];
    const float* b_out = (const float*)d_in[6];
    float* out = (float*)d_out;

    init_kernel<<<2, 1024>>>();
    const int logit_blocks = (VOCAB + 7) / 8;
    for (int t = 0; t < T_STEPS; t++) {
        gates_cell_kernel<<<256, 256>>>(emb, W_ih, W_hh, b_ih, b_hh, t);
        logits_kernel<<<logit_blocks, 256>>>(W_out, b_out, out, t);
    }
}

// round 2
// speedup vs baseline: 1.2045x; 1.2045x over previous
#include <cuda_runtime.h>
#include <cuda_fp16.h>
#include <math.h>

#define EMB   1024
#define HID   2048
#define VOCAB 50257
#define T_STEPS 256

// Persistent state across the 256 sequential steps. h double-buffered; c in-place
// (each element owned by one thread); g_key holds packed argmax
// (orderable float bits << 32 | (0xFFFFFFFF - index)), double-buffered.
__device__ __align__(16) float g_h[2][HID];
__device__ __align__(16) float g_c[HID];
__device__ unsigned long long g_key[2];

// fp16 copy of W_out (206 MB scratch as __device__ global, per harness rules).
__device__ __align__(16) __half g_wout_h[(size_t)VOCAB * HID];

__device__ __forceinline__ float sigmoidf_(float x) {
    return 1.0f / (1.0f + expf(-x));
}

__device__ __forceinline__ unsigned long long pack_key(float v, int idx) {
    unsigned ub = __float_as_uint(v);
    unsigned mk = (ub & 0x80000000u) ? ~ub : (ub | 0x80000000u);  // orderable float
    return ((unsigned long long)mk << 32) | (unsigned long long)(0xFFFFFFFFu - (unsigned)idx);
}

__global__ void init_kernel() {
    int tid = blockIdx.x * blockDim.x + threadIdx.x;
    for (int i = tid; i < HID; i += 2048) {
        g_h[0][i] = 0.0f;
        g_h[1][i] = 0.0f;
        g_c[i]    = 0.0f;
    }
    if (tid == 0) {
        g_key[0] = 0ull;
        g_key[1] = 0xFFFFFFFFull;  // decodes to token 0 for step 0
    }
}

// Convert W_out fp32 -> fp16. Grid exactly covers VOCAB*HID/8 threads.
__global__ void __launch_bounds__(256) wout_convert_kernel(const float* __restrict__ W_out) {
    size_t i = (size_t)blockIdx.x * 256 + threadIdx.x;   // one uint4 (8 halves) per thread
    const float4* p = (const float4*)W_out + 2 * i;
    float4 a = __ldcs(p);
    float4 b = __ldcs(p + 1);
    __half2 h0 = __floats2half2_rn(a.x, a.y);
    __half2 h1 = __floats2half2_rn(a.z, a.w);
    __half2 h2 = __floats2half2_rn(b.x, b.y);
    __half2 h3 = __floats2half2_rn(b.z, b.w);
    uint4 o;
    o.x = *(unsigned*)&h0; o.y = *(unsigned*)&h1;
    o.z = *(unsigned*)&h2; o.w = *(unsigned*)&h3;
    ((uint4*)g_wout_h)[i] = o;
}

// Gates + cell update. Split-K x2: two warps per hidden index j (half each of the
// x-dot and h-dot), combined in shared. Grid: 512 blocks x 256 threads = 4096 warps.
__global__ void __launch_bounds__(256) gates_cell_kernel(
    const float* __restrict__ emb,
    const float* __restrict__ W_ih,
    const float* __restrict__ W_hh,
    const float* __restrict__ b_ih,
    const float* __restrict__ b_hh,
    int t)
{
    __shared__ __align__(16) float sx[EMB];
    __shared__ __align__(16) float sh[HID];
    __shared__ float spart[8][4];

    const int tid  = threadIdx.x;
    const int lane = tid & 31;
    const int warp = tid >> 5;
    const int jl   = warp >> 1;      // 0..3: hidden index within block
    const int half = warp & 1;       // which K-half this warp handles

    // Token from previous step's refine.
    unsigned long long key = g_key[(t + 1) & 1];
    int tok = (int)(0xFFFFFFFFu - (unsigned)(key & 0xFFFFFFFFull));

    // Stage x = emb[tok] and h.
    const float4* xe = (const float4*)(emb + (size_t)tok * EMB);
    ((float4*)sx)[tid] = xe[tid];                       // 256 float4 = 1024 floats
    const float4* h4 = (const float4*)(g_h[t & 1]);
    ((float4*)sh)[tid]       = h4[tid];
    ((float4*)sh)[tid + 256] = h4[tid + 256];
    __syncthreads();

    const int j = blockIdx.x * 4 + jl;                  // 0..2047

    float a0 = 0.f, a1 = 0.f, a2 = 0.f, a3 = 0.f;

    // x-dot: this warp covers EMB/2 = 512 floats -> 4 iters of float4 per lane.
    {
        const int base = half * (EMB / 2 / 4);          // float4 offset into the row
        const float4* wi0 = (const float4*)(W_ih + (size_t)(j          ) * EMB) + base;
        const float4* wi1 = (const float4*)(W_ih + (size_t)(j +     HID) * EMB) + base;
        const float4* wi2 = (const float4*)(W_ih + (size_t)(j + 2 * HID) * EMB) + base;
        const float4* wi3 = (const float4*)(W_ih + (size_t)(j + 3 * HID) * EMB) + base;
        const float4* sx4 = (const float4*)sx + base;
        #pragma unroll
        for (int it = 0; it < 4; it++) {
            int idx = it * 32 + lane;
            float4 xv = sx4[idx];
            float4 v0 = __ldg(&wi0[idx]);
            float4 v1 = __ldg(&wi1[idx]);
            float4 v2 = __ldg(&wi2[idx]);
            float4 v3 = __ldg(&wi3[idx]);
            a0 += v0.x * xv.x + v0.y * xv.y + v0.z * xv.z + v0.w * xv.w;
            a1 += v1.x * xv.x + v1.y * xv.y + v1.z * xv.z + v1.w * xv.w;
            a2 += v2.x * xv.x + v2.y * xv.y + v2.z * xv.z + v2.w * xv.w;
            a3 += v3.x * xv.x + v3.y * xv.y + v3.z * xv.z + v3.w * xv.w;
        }
    }

    // h-dot: this warp covers HID/2 = 1024 floats -> 8 iters of float4 per lane.
    {
        const int base = half * (HID / 2 / 4);
        const float4* wh0 = (const float4*)(W_hh + (size_t)(j          ) * HID) + base;
        const float4* wh1 = (const float4*)(W_hh + (size_t)(j +     HID) * HID) + base;
        const float4* wh2 = (const float4*)(W_hh + (size_t)(j + 2 * HID) * HID) + base;
        const float4* wh3 = (const float4*)(W_hh + (size_t)(j + 3 * HID) * HID) + base;
        const float4* sh4 = (const float4*)sh + base;
        #pragma unroll
        for (int it = 0; it < 8; it++) {
            int idx = it * 32 + lane;
            float4 hv = sh4[idx];
            float4 v0 = __ldg(&wh0[idx]);
            float4 v1 = __ldg(&wh1[idx]);
            float4 v2 = __ldg(&wh2[idx]);
            float4 v3 = __ldg(&wh3[idx]);
            a0 += v0.x * hv.x + v0.y * hv.y + v0.z * hv.z + v0.w * hv.w;
            a1 += v1.x * hv.x + v1.y * hv.y + v1.z * hv.z + v1.w * hv.w;
            a2 += v2.x * hv.x + v2.y * hv.y + v2.z * hv.z + v2.w * hv.w;
            a3 += v3.x * hv.x + v3.y * hv.y + v3.z * hv.z + v3.w * hv.w;
        }
    }

    #pragma unroll
    for (int off = 16; off > 0; off >>= 1) {
        a0 += __shfl_xor_sync(0xFFFFFFFFu, a0, off);
        a1 += __shfl_xor_sync(0xFFFFFFFFu, a1, off);
        a2 += __shfl_xor_sync(0xFFFFFFFFu, a2, off);
        a3 += __shfl_xor_sync(0xFFFFFFFFu, a3, off);
    }
    if (lane == 0) {
        spart[warp][0] = a0; spart[warp][1] = a1;
        spart[warp][2] = a2; spart[warp][3] = a3;
    }
    __syncthreads();

    if (tid < 4) {                                      // tid == jl, combine halves
        const int jj = blockIdx.x * 4 + tid;
        float s0 = spart[2 * tid][0] + spart[2 * tid + 1][0]
                 + b_ih[jj          ] + b_hh[jj          ];
        float s1 = spart[2 * tid][1] + spart[2 * tid + 1][1]
                 + b_ih[jj +     HID] + b_hh[jj +     HID];
        float s2 = spart[2 * tid][2] + spart[2 * tid + 1][2]
                 + b_ih[jj + 2 * HID] + b_hh[jj + 2 * HID];
        float s3 = spart[2 * tid][3] + spart[2 * tid + 1][3]
                 + b_ih[jj + 3 * HID] + b_hh[jj + 3 * HID];
        float ig = sigmoidf_(s0);
        float fg = sigmoidf_(s1);
        float gg = tanhf(s2);
        float og = sigmoidf_(s3);
        float c  = fg * g_c[jj] + ig * gg;
        g_c[jj] = c;
        g_h[(t + 1) & 1][jj] = og * tanhf(c);
    }
}

// fp16 logits matvec: warp handles 2 rows (16 uint4 loads in flight), streaming loads.
// Grid: ceil(VOCAB/16) x 256.
__global__ void __launch_bounds__(256) logits_fp16_kernel(
    const float* __restrict__ b_out,
    float* __restrict__ out,
    int t)
{
    __shared__ __align__(16) float sh[HID];

    const int tid  = threadIdx.x;
    const int lane = tid & 31;
    const int warp = tid >> 5;

    const float4* h4 = (const float4*)(g_h[(t + 1) & 1]);
    ((float4*)sh)[tid]       = h4[tid];
    ((float4*)sh)[tid + 256] = h4[tid + 256];
    __syncthreads();

    const int v0 = blockIdx.x * 16 + warp * 2;
    const int v1 = v0 + 1;
    const bool p0 = v0 < VOCAB;
    const bool p1 = v1 < VOCAB;

    const uint4* w0 = (const uint4*)(g_wout_h + (size_t)v0 * HID);
    const uint4* w1 = (const uint4*)(g_wout_h + (size_t)v1 * HID);
    const float4* sh4 = (const float4*)sh;

    float acc0 = 0.f, acc1 = 0.f;
    #pragma unroll
    for (int it = 0; it < 8; it++) {                    // 2048 halves / (32 lanes * 8) = 8
        int idx = it * 32 + lane;
        float4 ha = sh4[2 * idx];
        float4 hb = sh4[2 * idx + 1];
        if (p0) {
            uint4 wv = __ldcs(&w0[idx]);
            float2 f0 = __half22float2(*(__half2*)&wv.x);
            float2 f1 = __half22float2(*(__half2*)&wv.y);
            float2 f2 = __half22float2(*(__half2*)&wv.z);
            float2 f3 = __half22float2(*(__half2*)&wv.w);
            acc0 += f0.x * ha.x + f0.y * ha.y + f1.x * ha.z + f1.y * ha.w
                  + f2.x * hb.x + f2.y * hb.y + f3.x * hb.z + f3.y * hb.w;
        }
        if (p1) {
            uint4 wv = __ldcs(&w1[idx]);
            float2 f0 = __half22float2(*(__half2*)&wv.x);
            float2 f1 = __half22float2(*(__half2*)&wv.y);
            float2 f2 = __half22float2(*(__half2*)&wv.z);
            float2 f3 = __half22float2(*(__half2*)&wv.w);
            acc1 += f0.x * ha.x + f0.y * ha.y + f1.x * ha.z + f1.y * ha.w
                  + f2.x * hb.x + f2.y * hb.y + f3.x * hb.z + f3.y * hb.w;
        }
    }
    #pragma unroll
    for (int off = 16; off > 0; off >>= 1) {
        acc0 += __shfl_xor_sync(0xFFFFFFFFu, acc0, off);
        acc1 += __shfl_xor_sync(0xFFFFFFFFu, acc1, off);
    }
    if (lane == 0 && p0) __stcs(&out[(size_t)t * VOCAB + v0], acc0 + __ldg(&b_out[v0]));
    if (lane == 0 && p1) __stcs(&out[(size_t)t * VOCAB + v1], acc1 + __ldg(&b_out[v1]));
}

// Refine: scan this step's logits for the global top-3 (packed keys, first-index
// tie rule), recompute those exactly in fp32, write the argmax token key.
__global__ void __launch_bounds__(1024) refine_kernel(
    const float* __restrict__ W_out,
    const float* __restrict__ b_out,
    const float* __restrict__ out,
    int t)
{
    __shared__ unsigned long long stop[32][3];
    __shared__ unsigned long long gtop[3];
    __shared__ unsigned long long res[3];

    const int tid  = threadIdx.x;
    const int lane = tid & 31;
    const int warp = tid >> 5;
    const float* lg = out + (size_t)t * VOCAB;

    // Thread-local top-3 (keys globally unique: one per index).
    unsigned long long k0 = 0, k1 = 0, k2 = 0;
    for (int v = tid; v < VOCAB; v += 1024) {
        unsigned long long key = pack_key(lg[v], v);
        if (key > k0)      { k2 = k1; k1 = k0; k0 = key; }
        else if (key > k1) { k2 = k1; k1 = key; }
        else if (key > k2) { k2 = key; }
    }
    // Warp top-3: 3 rounds of warp-max + pop from the owner's sorted list.
    #pragma unroll
    for (int r = 0; r < 3; r++) {
        unsigned long long m = k0;
        #pragma unroll
        for (int off = 16; off > 0; off >>= 1) {
            unsigned long long o = __shfl_xor_sync(0xFFFFFFFFu, m, off);
            if (o > m) m = o;
        }
        if (k0 == m) { k0 = k1; k1 = k2; k2 = 0; }
        if (lane == 0) stop[warp][r] = m;
    }
    __syncthreads();
    if (warp == 0) {
        k0 = stop[lane][0]; k1 = stop[lane][1]; k2 = stop[lane][2];
        #pragma unroll
        for (int r = 0; r < 3; r++) {
            unsigned long long m = k0;
            #pragma unroll
            for (int off = 16; off > 0; off >>= 1) {
                unsigned long long o = __shfl_xor_sync(0xFFFFFFFFu, m, off);
                if (o > m) m = o;
            }
            if (k0 == m) { k0 = k1; k1 = k2; k2 = 0; }
            if (lane == 0) gtop[r] = m;
        }
    }
    __syncthreads();

    // Exact fp32 recompute for the 3 candidates (one warp each).
    if (warp < 3) {
        unsigned long long key = gtop[warp];
        int v = (int)(0xFFFFFFFFu - (unsigned)(key & 0xFFFFFFFFull));
        const float4* w  = (const float4*)(W_out + (size_t)v * HID);
        const float4* h4 = (const float4*)(g_h[(t + 1) & 1]);
        float acc = 0.f;
        #pragma unroll
        for (int it = 0; it < 16; it++) {
            int idx = it * 32 + lane;
            float4 wv = __ldg(&w[idx]);
            float4 hv = __ldg(&h4[idx]);
            acc += wv.x * hv.x + wv.y * hv.y + wv.z * hv.z + wv.w * hv.w;
        }
        #pragma unroll
        for (int off = 16; off > 0; off >>= 1)
            acc += __shfl_xor_sync(0xFFFFFFFFu, acc, off);
        if (lane == 0) res[warp] = pack_key(acc + __ldg(&b_out[v]), v);
    }
    __syncthreads();
    if (tid == 0) {
        unsigned long long best = res[0];
        if (res[1] > best) best = res[1];
        if (res[2] > best) best = res[2];
        g_key[t & 1] = best;
    }
}

extern "C" void kernel_launch(void* const* d_in, const int* in_sizes, int n_in,
                              void* d_out, int out_size)
{
    const float* emb   = (const float*)d_in[0];
    const float* W_ih  = (const float*)d_in[1];
    const float* W_hh  = (const float*)d_in[2];
    const float* b_ih  = (const float*)d_in[3];
    const float* b_hh  = (const float*)d_in[4];
    const float* W_out = (const float*)d_in[5];
    const float* b_out = (const float*)d_in[6];
    float* out = (float*)d_out;

    init_kernel<<<2, 1024>>>();
    wout_convert_kernel<<<VOCAB, 256>>>(W_out);          // VOCAB*HID/8 threads exactly

    const int logit_blocks = (VOCAB + 15) / 16;
    for (int t = 0; t < T_STEPS; t++) {
        gates_cell_kernel<<<512, 256>>>(emb, W_ih, W_hh, b_ih, b_hh, t);
        logits_fp16_kernel<<<logit_blocks, 256>>>(b_out, out, t);
        refine_kernel<<<1, 1024>>>(W_out, b_out, out, t);
    }
}